// round 5
// baseline (speedup 1.0000x reference)
#include <cuda_runtime.h>
#include <cstdint>

#define BB 8192      // batch rows
#define NN 4096      // feature dim
#define PADF 68      // smem row pitch in floats (16B-aligned, conflict-free)

// 128 MB scratch for the intermediate (B, 4096) tensor.
__device__ float g_scratch[(size_t)BB * NN];

__device__ __forceinline__ uint32_t f2tf32(float f) {
    uint32_t r;
    asm("cvt.rna.tf32.f32 %0, %1;" : "=r"(r) : "f"(f));
    return r;
}

__device__ __forceinline__ void mma16n8k8(float* d, const uint32_t* a,
                                          uint32_t b0, uint32_t b1) {
    asm volatile(
        "mma.sync.aligned.m16n8k8.row.col.f32.tf32.tf32.f32 "
        "{%0,%1,%2,%3}, {%4,%5,%6,%7}, {%8,%9}, {%0,%1,%2,%3};"
        : "+f"(d[0]), "+f"(d[1]), "+f"(d[2]), "+f"(d[3])
        : "r"(a[0]), "r"(a[1]), "r"(a[2]), "r"(a[3]), "r"(b0), "r"(b1));
}

// ---------------------------------------------------------------------------
// Stage 1: one CTA = 128 rows x one 64x64 block (j).  (unchanged, ~63us)
//   C[(m0+row)*4096 + j*64 + q] = sum_p A[(m0+row)*4096 + j*64 + p] * W[j,q,p]
// ---------------------------------------------------------------------------
__global__ __launch_bounds__(128) void gemm_mma(const float* __restrict__ A,
                                                const float* __restrict__ W,
                                                float* __restrict__ C) {
    extern __shared__ __align__(16) uint32_t sm[];
    uint32_t* As = sm;                 // 128 * 68
    uint32_t* Ws = sm + 128 * PADF;    //  64 * 68

    const int tid  = threadIdx.x;
    const int warp = tid >> 5;
    const int lane = tid & 31;
    const int g    = lane >> 2;
    const int t    = lane & 3;
    const int m0   = blockIdx.x * 128;
    const int j    = blockIdx.y;

    {
        const float* Ag = A + (size_t)m0 * NN + j * 64;
#pragma unroll
        for (int i = 0; i < 16; i++) {
            const int g4  = tid + i * 128;
            const int row = g4 >> 4;
            const int c4  = (g4 & 15) * 4;
            const float4 v = *(const float4*)(Ag + (size_t)row * NN + c4);
            uint32_t* d = As + row * PADF + c4;
            d[0] = f2tf32(v.x); d[1] = f2tf32(v.y);
            d[2] = f2tf32(v.z); d[3] = f2tf32(v.w);
        }
    }
    {
        const float* Wg = W + (size_t)j * 4096;
#pragma unroll
        for (int i = 0; i < 8; i++) {
            const int g4 = tid + i * 128;
            const int q  = g4 >> 4;
            const int c4 = (g4 & 15) * 4;
            const float4 v = *(const float4*)(Wg + q * 64 + c4);
            uint32_t* d = Ws + q * PADF + c4;
            d[0] = f2tf32(v.x); d[1] = f2tf32(v.y);
            d[2] = f2tf32(v.z); d[3] = f2tf32(v.w);
        }
    }
    __syncthreads();

    float acc[2][8][4] = {};
    const int rb0 = warp * 32;
#pragma unroll
    for (int ks = 0; ks < 8; ks++) {
        const int k0 = ks * 8;
        uint32_t a[2][4];
#pragma unroll
        for (int mi = 0; mi < 2; mi++) {
            const int rb = rb0 + mi * 16;
            a[mi][0] = As[(rb + g)     * PADF + k0 + t];
            a[mi][1] = As[(rb + g + 8) * PADF + k0 + t];
            a[mi][2] = As[(rb + g)     * PADF + k0 + t + 4];
            a[mi][3] = As[(rb + g + 8) * PADF + k0 + t + 4];
        }
#pragma unroll
        for (int ni = 0; ni < 8; ni++) {
            const uint32_t b0 = Ws[(ni * 8 + g) * PADF + k0 + t];
            const uint32_t b1 = Ws[(ni * 8 + g) * PADF + k0 + t + 4];
            mma16n8k8(acc[0][ni], a[0], b0, b1);
            mma16n8k8(acc[1][ni], a[1], b0, b1);
        }
    }

    float* Cg = C + (size_t)m0 * NN + j * 64;
#pragma unroll
    for (int mi = 0; mi < 2; mi++) {
        const int r0 = rb0 + mi * 16 + g;
#pragma unroll
        for (int ni = 0; ni < 8; ni++) {
            const int col = ni * 8 + t * 2;
            *(float2*)(Cg + (size_t)r0 * NN + col) =
                make_float2(acc[mi][ni][0], acc[mi][ni][1]);
            *(float2*)(Cg + (size_t)(r0 + 8) * NN + col) =
                make_float2(acc[mi][ni][2], acc[mi][ni][3]);
        }
    }
}

// ---------------------------------------------------------------------------
// Stage 2 fused: input permutation + GEMM + output permutation.
//   perm[b, l*64+r]  = out1[b, r*64+l]        (read fused, 4-l groups)
//   out2[b, l, s]    = sum_r perm[b,l,r] * w2[l,s,r]
//   out[b, s*64+l]   = out2[b, l, s]          (write fused via smem staging)
// CTA: 32 rows x 4 l-blocks, 256 threads = 8 warps; warp = (lw, row-half).
// Smem: A 4*32*68 + W 4*64*68 words = 102 KB  ->  2 CTAs/SM.
// ---------------------------------------------------------------------------
#define S2_ROWS 32
#define S2_G    4
#define S2_APITCH (S2_ROWS * PADF)       // 2176 words per l-region
#define S2_WPITCH (64 * PADF)            // 4352 words per l-region
#define S2_EPIT 260                      // epilogue row pitch (words)

__global__ __launch_bounds__(256) void gemm_s2_fused(const float* __restrict__ A,
                                                     const float* __restrict__ W,
                                                     float* __restrict__ out) {
    extern __shared__ __align__(16) uint32_t sm[];
    uint32_t* As = sm;                         // 4 * 2176 =  8704 words
    uint32_t* Ws = sm + S2_G * S2_APITCH;      // 4 * 4352 = 17408 words

    const int tid  = threadIdx.x;
    const int warp = tid >> 5;
    const int lane = tid & 31;
    const int g    = lane >> 2;
    const int t    = lane & 3;
    const int m0   = blockIdx.x * S2_ROWS;
    const int l0   = blockIdx.y * S2_G;

    // ---- load A: permuted tile; each (b, r) is a 16B chunk along l ----
    // element (b, r, dl) from A[(m0+b)*4096 + r*64 + l0 + dl]
#pragma unroll
    for (int i = 0; i < 8; i++) {
        const int g4 = tid + i * 256;          // 0..2047
        const int b  = g4 >> 6;                // 0..31
        const int r  = g4 & 63;                // 0..63
        const float4 v = *(const float4*)(A + (size_t)(m0 + b) * NN + r * 64 + l0);
        uint32_t* d = As + b * PADF + r;
        d[0 * S2_APITCH] = f2tf32(v.x);
        d[1 * S2_APITCH] = f2tf32(v.y);
        d[2 * S2_APITCH] = f2tf32(v.z);
        d[3 * S2_APITCH] = f2tf32(v.w);
    }
    // ---- load W: w2[l, s, r] for l in group ----
#pragma unroll
    for (int i = 0; i < 16; i++) {
        const int g4 = tid + i * 256;          // 0..4095
        const int ls = g4 >> 4;                // l*64 + s  (0..255)
        const int l  = ls >> 6;
        const int s  = ls & 63;
        const int c4 = (g4 & 15) * 4;
        const float4 v = *(const float4*)(W + (size_t)(l0 + l) * 4096 + s * 64 + c4);
        uint32_t* d = Ws + l * S2_WPITCH + s * PADF + c4;
        d[0] = f2tf32(v.x); d[1] = f2tf32(v.y);
        d[2] = f2tf32(v.z); d[3] = f2tf32(v.w);
    }
    __syncthreads();

    // ---- main loop: warp = (lw, rh); warp tile 16(M=b) x 64(N=s), K=r ----
    const int lw = warp >> 1;                  // l-block in group (0..3)
    const int rh = warp & 1;                   // row half (0..1)
    const uint32_t* Aw = As + lw * S2_APITCH + (rh * 16) * PADF;
    const uint32_t* Ww = Ws + lw * S2_WPITCH;

    float acc[8][4] = {};
#pragma unroll
    for (int ks = 0; ks < 8; ks++) {
        const int k0 = ks * 8;
        uint32_t a[4];
        a[0] = Aw[(g)     * PADF + k0 + t];
        a[1] = Aw[(g + 8) * PADF + k0 + t];
        a[2] = Aw[(g)     * PADF + k0 + t + 4];
        a[3] = Aw[(g + 8) * PADF + k0 + t + 4];
#pragma unroll
        for (int ni = 0; ni < 8; ni++) {
            const uint32_t b0 = Ww[(ni * 8 + g) * PADF + k0 + t];
            const uint32_t b1 = Ww[(ni * 8 + g) * PADF + k0 + t + 4];
            mma16n8k8(acc[ni], a, b0, b1);
        }
    }
    __syncthreads();   // done reading As/Ws; reuse As as epilogue staging

    // ---- epilogue: stage to st[b][s + 64*lw], then coalesced permuted write ----
    float* st = (float*)As;                    // 32 * 260 = 8320 words <= 8704
    {
        const int r0 = rh * 16 + g;
#pragma unroll
        for (int ni = 0; ni < 8; ni++) {
            const int s = ni * 8 + t * 2;
            *(float2*)(st + r0 * S2_EPIT + s + 64 * lw) =
                make_float2(acc[ni][0], acc[ni][1]);
            *(float2*)(st + (r0 + 8) * S2_EPIT + s + 64 * lw) =
                make_float2(acc[ni][2], acc[ni][3]);
        }
    }
    __syncthreads();
    // out[(m0+b)*4096 + s*64 + l0 + dl] = st[b][s + 64*dl]
#pragma unroll
    for (int i = 0; i < 8; i++) {
        const int g4 = tid + i * 256;          // 0..2047
        const int b  = g4 >> 6;
        const int s  = g4 & 63;
        const float* p = st + b * S2_EPIT + s;
        float4 v = make_float4(p[0], p[64], p[128], p[192]);
        *(float4*)(out + (size_t)(m0 + b) * NN + s * 64 + l0) = v;
    }
}

extern "C" void kernel_launch(void* const* d_in, const int* in_sizes, int n_in,
                              void* d_out, int out_size) {
    const float* x  = (const float*)d_in[0];   // (8192, 4096)
    const float* w1 = (const float*)d_in[1];   // (64, 64, 64)
    const float* w2 = (const float*)d_in[2];   // (64, 64, 64)
    float* out = (float*)d_out;

    float* scratch = nullptr;
    cudaGetSymbolAddress((void**)&scratch, g_scratch);

    const int smem1 = (128 * PADF + 64 * PADF) * 4;                    // 52224
    const int smem2 = (S2_G * S2_APITCH + S2_G * S2_WPITCH) * 4;       // 104448
    cudaFuncSetAttribute(gemm_mma, cudaFuncAttributeMaxDynamicSharedMemorySize, smem1);
    cudaFuncSetAttribute(gemm_s2_fused, cudaFuncAttributeMaxDynamicSharedMemorySize, smem2);

    // Stage 1: natural-layout block GEMM
    dim3 g1(BB / 128, 64);
    gemm_mma<<<g1, 128, smem1>>>(x, w1, scratch);

    // Stage 2: fused permute -> GEMM -> permuted write
    dim3 g2(BB / S2_ROWS, 64 / S2_G);          // (256, 16)
    gemm_s2_fused<<<g2, 256, smem2>>>(scratch, w2, out);
}

// round 6
// speedup vs baseline: 1.4300x; 1.4300x over previous
#include <cuda_runtime.h>
#include <cstdint>

#define BB 8192      // batch rows
#define NN 4096      // feature dim
#define PADF 68      // stage-1 smem pitch (floats)

// 128 MB scratch for the intermediate (B, 4096) tensor.
__device__ float g_scratch[(size_t)BB * NN];

__device__ __forceinline__ uint32_t f2tf32(float f) {
    uint32_t r;
    asm("cvt.rna.tf32.f32 %0, %1;" : "=r"(r) : "f"(f));
    return r;
}

__device__ __forceinline__ void mma16n8k8(float* d, const uint32_t* a,
                                          uint32_t b0, uint32_t b1) {
    asm volatile(
        "mma.sync.aligned.m16n8k8.row.col.f32.tf32.tf32.f32 "
        "{%0,%1,%2,%3}, {%4,%5,%6,%7}, {%8,%9}, {%0,%1,%2,%3};"
        : "+f"(d[0]), "+f"(d[1]), "+f"(d[2]), "+f"(d[3])
        : "r"(a[0]), "r"(a[1]), "r"(a[2]), "r"(a[3]), "r"(b0), "r"(b1));
}

// ---------------------------------------------------------------------------
// Stage 1 (unchanged champion): one CTA = 128 rows x one 64x64 block (j).
//   C[(m0+row)*4096 + j*64 + q] = sum_p A[(m0+row)*4096 + j*64 + p] * W[j,q,p]
// ---------------------------------------------------------------------------
__global__ __launch_bounds__(128) void gemm_mma(const float* __restrict__ A,
                                                const float* __restrict__ W,
                                                float* __restrict__ C) {
    extern __shared__ __align__(16) uint32_t sm[];
    uint32_t* As = sm;                 // 128 * 68
    uint32_t* Ws = sm + 128 * PADF;    //  64 * 68

    const int tid  = threadIdx.x;
    const int warp = tid >> 5;
    const int lane = tid & 31;
    const int g    = lane >> 2;
    const int t    = lane & 3;
    const int m0   = blockIdx.x * 128;
    const int j    = blockIdx.y;

    {
        const float* Ag = A + (size_t)m0 * NN + j * 64;
#pragma unroll
        for (int i = 0; i < 16; i++) {
            const int g4  = tid + i * 128;
            const int row = g4 >> 4;
            const int c4  = (g4 & 15) * 4;
            const float4 v = *(const float4*)(Ag + (size_t)row * NN + c4);
            uint32_t* d = As + row * PADF + c4;
            d[0] = f2tf32(v.x); d[1] = f2tf32(v.y);
            d[2] = f2tf32(v.z); d[3] = f2tf32(v.w);
        }
    }
    {
        const float* Wg = W + (size_t)j * 4096;
#pragma unroll
        for (int i = 0; i < 8; i++) {
            const int g4 = tid + i * 128;
            const int q  = g4 >> 4;
            const int c4 = (g4 & 15) * 4;
            const float4 v = *(const float4*)(Wg + q * 64 + c4);
            uint32_t* d = Ws + q * PADF + c4;
            d[0] = f2tf32(v.x); d[1] = f2tf32(v.y);
            d[2] = f2tf32(v.z); d[3] = f2tf32(v.w);
        }
    }
    __syncthreads();

    float acc[2][8][4] = {};
    const int rb0 = warp * 32;
#pragma unroll
    for (int ks = 0; ks < 8; ks++) {
        const int k0 = ks * 8;
        uint32_t a[2][4];
#pragma unroll
        for (int mi = 0; mi < 2; mi++) {
            const int rb = rb0 + mi * 16;
            a[mi][0] = As[(rb + g)     * PADF + k0 + t];
            a[mi][1] = As[(rb + g + 8) * PADF + k0 + t];
            a[mi][2] = As[(rb + g)     * PADF + k0 + t + 4];
            a[mi][3] = As[(rb + g + 8) * PADF + k0 + t + 4];
        }
#pragma unroll
        for (int ni = 0; ni < 8; ni++) {
            const uint32_t b0 = Ws[(ni * 8 + g) * PADF + k0 + t];
            const uint32_t b1 = Ws[(ni * 8 + g) * PADF + k0 + t + 4];
            mma16n8k8(acc[0][ni], a[0], b0, b1);
            mma16n8k8(acc[1][ni], a[1], b0, b1);
        }
    }

    float* Cg = C + (size_t)m0 * NN + j * 64;
#pragma unroll
    for (int mi = 0; mi < 2; mi++) {
        const int r0 = rb0 + mi * 16 + g;
#pragma unroll
        for (int ni = 0; ni < 8; ni++) {
            const int col = ni * 8 + t * 2;
            *(float2*)(Cg + (size_t)r0 * NN + col) =
                make_float2(acc[mi][ni][0], acc[mi][ni][1]);
            *(float2*)(Cg + (size_t)(r0 + 8) * NN + col) =
                make_float2(acc[mi][ni][2], acc[mi][ni][3]);
        }
    }
}

// ---------------------------------------------------------------------------
// Stage 2, software-pipelined persistent version.
//   perm[b, l*64+r] = out1[b, r*64+l]          (fused read)
//   out2[b, l, s]   = sum_r perm[b,l,r] * w2[l,s,r]
//   out[b, s*64+l]  = out2[b, l, s]            (fused write via smem staging)
// CTA: 4 l-blocks, 8 chunks of 16 rows (persistent). 256 threads = 8 warps;
// warp = (lw = warp>>1, nh = warp&1), warp tile 16(M=b) x 32(N=s).
// Smem: W resident 4*64*64 tf32 (tight, XOR-4 swizzle) = 64KB
//       A double-buffer 2 * 4160 words = 33.3KB  -> total 96.5KB, 2 CTA/SM.
// Pipeline: LDG(next chunk)->regs overlaps MMA(cur); epilogue stages into
// the other A buffer (free: its chunk's MMA finished last iteration).
// ---------------------------------------------------------------------------
#define S2_G      4
#define S2_CH     16          // rows per chunk
#define S2_NCHUNK 8           // chunks per CTA (128 rows)
#define S2_WW     (S2_G * 64 * 64)   // W words = 16384
#define S2_AB     4160               // A buffer words (>= 4096 data, 16*260 epi)
#define S2_EPIT   260                // epilogue staging pitch (words)
#define S2_SMEM   ((S2_WW + 2 * S2_AB) * 4)   // 98816 bytes

__global__ __launch_bounds__(256) void gemm_s2_pipe(const float* __restrict__ A,
                                                    const float* __restrict__ W,
                                                    float* __restrict__ out) {
    extern __shared__ __align__(16) uint32_t sm[];
    uint32_t* Ws = sm;                          // swizzled W
    uint32_t* Ab0 = sm + S2_WW;
    uint32_t* Ab1 = sm + S2_WW + S2_AB;

    const int tid  = threadIdx.x;
    const int warp = tid >> 5;
    const int lane = tid & 31;
    const int g    = lane >> 2;       // 0..7
    const int t    = lane & 3;        // 0..3
    const int lw   = warp >> 1;       // l within group (0..3)
    const int nh   = warp & 1;        // n half (0..1)
    const int l0   = blockIdx.y * S2_G;
    const int row0 = blockIdx.x * (S2_CH * S2_NCHUNK);

    // ---- load W once: w2[l0+l, q, p] -> Ws[(l*64+q)*64 + (p ^ 4*(q&7))] ----
#pragma unroll
    for (int i = 0; i < 16; i++) {
        const int g4 = tid + i * 256;           // float4 index 0..4095
        const int lq = g4 >> 4;                 // l*64+q
        const int q  = lq & 63;
        const int p4 = (g4 & 15) * 4;
        const float4 v = *(const float4*)(W + (size_t)(l0 + (lq >> 6)) * 4096 + q * 64 + p4);
        uint32_t* d = Ws + lq * 64 + (p4 ^ (4 * (q & 7)));
        d[0] = f2tf32(v.x); d[1] = f2tf32(v.y);
        d[2] = f2tf32(v.z); d[3] = f2tf32(v.w);
    }

    // per-thread LDG targets for a chunk: 4 float4s, each = (b, r) chunk over l
    int bb[4], rr[4];
#pragma unroll
    for (int i = 0; i < 4; i++) {
        const int g4 = tid + i * 256;           // 0..1023
        bb[i] = g4 >> 6;                        // 0..15
        rr[i] = g4 & 63;                        // 0..63
    }

    // prefetch chunk 0
    float4 v[4];
#pragma unroll
    for (int i = 0; i < 4; i++)
        v[i] = *(const float4*)(A + (size_t)(row0 + bb[i]) * NN + rr[i] * 64 + l0);

    for (int c = 0; c < S2_NCHUNK; c++) {
        uint32_t* cur = (c & 1) ? Ab1 : Ab0;
        uint32_t* oth = (c & 1) ? Ab0 : Ab1;

        __syncthreads();   // prev STG reads + prev MMA reads of 'cur' complete

        // ---- STS chunk c (tf32 convert, XOR-4 swizzle) ----
#pragma unroll
        for (int i = 0; i < 4; i++) {
            const int b = bb[i], r = rr[i];
            const int sw = r ^ (4 * (b & 7));
            cur[(0 * 16 + b) * 64 + sw] = f2tf32(v[i].x);
            cur[(1 * 16 + b) * 64 + sw] = f2tf32(v[i].y);
            cur[(2 * 16 + b) * 64 + sw] = f2tf32(v[i].z);
            cur[(3 * 16 + b) * 64 + sw] = f2tf32(v[i].w);
        }
        // ---- prefetch chunk c+1 (overlaps MMA below) ----
        if (c + 1 < S2_NCHUNK) {
            const int rbase = row0 + (c + 1) * S2_CH;
#pragma unroll
            for (int i = 0; i < 4; i++)
                v[i] = *(const float4*)(A + (size_t)(rbase + bb[i]) * NN + rr[i] * 64 + l0);
        }
        __syncthreads();   // chunk c visible

        // ---- MMA: warp tile 16(M) x 32(N) over K=64 ----
        const uint32_t* Aw = cur + lw * 16 * 64;
        const uint32_t* Wb = Ws + (lw * 64 + nh * 32) * 64;
        float acc[4][4] = {{0}};
#pragma unroll
        for (int ks = 0; ks < 8; ks++) {
            const int k0 = ks * 8;
            const int sa = 4 * (g & 7);
            uint32_t a[4];
            a[0] = Aw[(g)     * 64 + ((k0 + t)     ^ sa)];
            a[1] = Aw[(g + 8) * 64 + ((k0 + t)     ^ sa)];
            a[2] = Aw[(g)     * 64 + ((k0 + t + 4) ^ sa)];
            a[3] = Aw[(g + 8) * 64 + ((k0 + t + 4) ^ sa)];
#pragma unroll
            for (int ni = 0; ni < 4; ni++) {
                const uint32_t b0 = Wb[(ni * 8 + g) * 64 + ((k0 + t)     ^ sa)];
                const uint32_t b1 = Wb[(ni * 8 + g) * 64 + ((k0 + t + 4) ^ sa)];
                mma16n8k8(acc[ni], a, b0, b1);
            }
        }

        // ---- stage epilogue into the other buffer: st[b][s + 64*lw] ----
        float* st = (float*)oth;
#pragma unroll
        for (int ni = 0; ni < 4; ni++) {
            const int s = nh * 32 + ni * 8 + t * 2;
            *(float2*)(st + (g)     * S2_EPIT + s + 64 * lw) =
                make_float2(acc[ni][0], acc[ni][1]);
            *(float2*)(st + (g + 8) * S2_EPIT + s + 64 * lw) =
                make_float2(acc[ni][2], acc[ni][3]);
        }
        __syncthreads();   // staged values visible

        // ---- coalesced permuted write: out[b, s*64 + l0+dl] ----
        const int brow = row0 + c * S2_CH;
#pragma unroll
        for (int i = 0; i < 4; i++) {
            const int g4 = tid + i * 256;       // 0..1023
            const int b  = g4 >> 6;
            const int s  = g4 & 63;
            const float* p = st + b * S2_EPIT + s;
            float4 o = make_float4(p[0], p[64], p[128], p[192]);
            *(float4*)(out + (size_t)(brow + b) * NN + s * 64 + l0) = o;
        }
    }
}

extern "C" void kernel_launch(void* const* d_in, const int* in_sizes, int n_in,
                              void* d_out, int out_size) {
    const float* x  = (const float*)d_in[0];   // (8192, 4096)
    const float* w1 = (const float*)d_in[1];   // (64, 64, 64)
    const float* w2 = (const float*)d_in[2];   // (64, 64, 64)
    float* out = (float*)d_out;

    float* scratch = nullptr;
    cudaGetSymbolAddress((void**)&scratch, g_scratch);

    const int smem1 = (128 * PADF + 64 * PADF) * 4;   // 52224
    cudaFuncSetAttribute(gemm_mma, cudaFuncAttributeMaxDynamicSharedMemorySize, smem1);
    cudaFuncSetAttribute(gemm_s2_pipe, cudaFuncAttributeMaxDynamicSharedMemorySize, S2_SMEM);

    // Stage 1: natural-layout block GEMM -> scratch
    dim3 g1(BB / 128, 64);
    gemm_mma<<<g1, 128, smem1>>>(x, w1, scratch);

    // Stage 2: pipelined fused permute -> GEMM -> permuted write
    dim3 g2(BB / (S2_CH * S2_NCHUNK), 64 / S2_G);     // (64, 16) = 1024 CTAs
    gemm_s2_pipe<<<g2, 256, S2_SMEM>>>(scratch, w2, out);
}

// round 7
// speedup vs baseline: 1.8488x; 1.2929x over previous
#include <cuda_runtime.h>
#include <cstdint>

#define BB 8192      // batch rows
#define NN 4096      // feature dim

// 128 MB scratch for the intermediate (B, 4096) tensor.
__device__ float g_scratch[(size_t)BB * NN];

__device__ __forceinline__ uint32_t f2tf32(float f) {
    uint32_t r;
    asm("cvt.rna.tf32.f32 %0, %1;" : "=r"(r) : "f"(f));
    return r;
}

__device__ __forceinline__ void mma16n8k8(float* d, const uint32_t* a,
                                          uint32_t b0, uint32_t b1) {
    asm volatile(
        "mma.sync.aligned.m16n8k8.row.col.f32.tf32.tf32.f32 "
        "{%0,%1,%2,%3}, {%4,%5,%6,%7}, {%8,%9}, {%0,%1,%2,%3};"
        : "+f"(d[0]), "+f"(d[1]), "+f"(d[2]), "+f"(d[3])
        : "r"(a[0]), "r"(a[1]), "r"(a[2]), "r"(a[3]), "r"(b0), "r"(b1));
}

// ---------------------------------------------------------------------------
// Block GEMM, high-occupancy version: one CTA = 64 rows x one 64x64 block (j).
//   C[(m0+row)*4096 + j*64 + q] = sum_p A[(m0+row)*4096 + j*64 + p] * W[j,q,p]
// Smem: A 64x64 + W 64x64 tf32, tight pitch with XOR-4 swizzle
//   word(row, k) = row*64 + (k ^ (4*(row&7)))
// -> 32 KB static smem, 128 threads -> 7 CTAs/SM (28 warps, 44% occ).
// Swizzle is conflict-free for float4 STS (bits 2..4 XOR) and for MMA
// fragment LDS (bank = (t ^ 4g) + k0 spans 32 distinct banks). Proven in R6.
// 4 warps; warp tile 16(M) x 64(N); K=64 in 8 ksteps.
// ---------------------------------------------------------------------------
__global__ __launch_bounds__(128) void gemm64s(const float* __restrict__ A,
                                               const float* __restrict__ W,
                                               float* __restrict__ C) {
    __shared__ __align__(16) uint32_t As[64 * 64];
    __shared__ __align__(16) uint32_t Ws[64 * 64];

    const int tid  = threadIdx.x;
    const int warp = tid >> 5;
    const int lane = tid & 31;
    const int g    = lane >> 2;        // 0..7
    const int t    = lane & 3;         // 0..3
    const int m0   = blockIdx.x * 64;
    const int j    = blockIdx.y;

    // ---- load A tile 64x64 (coalesced float4), tf32 convert, swizzled ----
    {
        const float* Ag = A + (size_t)m0 * NN + j * 64;
#pragma unroll
        for (int i = 0; i < 8; i++) {
            const int g4  = tid + i * 128;     // 0..1023
            const int row = g4 >> 4;
            const int c4  = (g4 & 15) * 4;
            const float4 v = *(const float4*)(Ag + (size_t)row * NN + c4);
            uint32_t* d = As + row * 64 + (c4 ^ (4 * (row & 7)));
            d[0] = f2tf32(v.x); d[1] = f2tf32(v.y);
            d[2] = f2tf32(v.z); d[3] = f2tf32(v.w);
        }
    }
    // ---- load W tile 64(q) x 64(p) ----
    {
        const float* Wg = W + (size_t)j * 4096;
#pragma unroll
        for (int i = 0; i < 8; i++) {
            const int g4 = tid + i * 128;
            const int q  = g4 >> 4;
            const int c4 = (g4 & 15) * 4;
            const float4 v = *(const float4*)(Wg + q * 64 + c4);
            uint32_t* d = Ws + q * 64 + (c4 ^ (4 * (q & 7)));
            d[0] = f2tf32(v.x); d[1] = f2tf32(v.y);
            d[2] = f2tf32(v.z); d[3] = f2tf32(v.w);
        }
    }
    __syncthreads();

    // ---- main loop: warp tile 16(M) x 64(N) ----
    const int rb0 = warp * 16;
    float acc[8][4] = {{0}};
#pragma unroll
    for (int ks = 0; ks < 8; ks++) {
        const int k0 = ks * 8;
        const int sa = 4 * g;              // (row&7)==g for rows g and g+8
        uint32_t a[4];
        a[0] = As[(rb0 + g)     * 64 + ((k0 + t)     ^ sa)];
        a[1] = As[(rb0 + g + 8) * 64 + ((k0 + t)     ^ sa)];
        a[2] = As[(rb0 + g)     * 64 + ((k0 + t + 4) ^ sa)];
        a[3] = As[(rb0 + g + 8) * 64 + ((k0 + t + 4) ^ sa)];
#pragma unroll
        for (int ni = 0; ni < 8; ni++) {
            const uint32_t b0 = Ws[(ni * 8 + g) * 64 + ((k0 + t)     ^ sa)];
            const uint32_t b1 = Ws[(ni * 8 + g) * 64 + ((k0 + t + 4) ^ sa)];
            mma16n8k8(acc[ni], a, b0, b1);
        }
    }

    // ---- epilogue: direct float2 stores (sector-exact) ----
    float* Cg = C + (size_t)m0 * NN + j * 64;
    const int r0 = rb0 + g;
#pragma unroll
    for (int ni = 0; ni < 8; ni++) {
        const int col = ni * 8 + t * 2;
        *(float2*)(Cg + (size_t)r0 * NN + col) =
            make_float2(acc[ni][0], acc[ni][1]);
        *(float2*)(Cg + (size_t)(r0 + 8) * NN + col) =
            make_float2(acc[ni][2], acc[ni][3]);
    }
}

// ---------------------------------------------------------------------------
// Per-row 64x64 transpose: out[b, i*64 + j] = in[b, j*64 + i]. In-place safe.
// (~82% of practical HBM; unchanged from R3 champion.)
// ---------------------------------------------------------------------------
__global__ __launch_bounds__(256) void trans64(const float* __restrict__ in,
                                               float* __restrict__ out) {
    __shared__ float smt[64][65];
    const int b   = blockIdx.x;
    const int tid = threadIdx.x;
    const float* ip = in  + (size_t)b * NN;
    float*       op = out + (size_t)b * NN;

#pragma unroll
    for (int i = 0; i < 16; i++) {
        const int t = tid + i * 256;
        smt[t & 63][t >> 6] = ip[t];
    }
    __syncthreads();
#pragma unroll
    for (int i = 0; i < 16; i++) {
        const int t = tid + i * 256;
        op[t] = smt[t >> 6][t & 63];
    }
}

extern "C" void kernel_launch(void* const* d_in, const int* in_sizes, int n_in,
                              void* d_out, int out_size) {
    const float* x  = (const float*)d_in[0];   // (8192, 4096)
    const float* w1 = (const float*)d_in[1];   // (64, 64, 64)
    const float* w2 = (const float*)d_in[2];   // (64, 64, 64)
    float* out = (float*)d_out;

    float* scratch = nullptr;
    cudaGetSymbolAddress((void**)&scratch, g_scratch);

    dim3 ggrid(BB / 64, 64);   // (128, 64) = 8192 CTAs

    // Stage 1: out1[b, k*64+q] = sum_p x[b, k*64+p] * w1[k, q, p]
    gemm64s<<<ggrid, 128>>>(x, w1, scratch);
    // Permutation: (b, r*64+l) -> (b, l*64+r)
    trans64<<<BB, 256>>>(scratch, scratch);
    // Stage 2: out2[b, l*64+s] = sum_r perm[b, l*64+r] * w2[l, s, r]
    gemm64s<<<ggrid, 128>>>(scratch, w2, scratch);
    // Final permutation: out[b, s*64+l] = out2[b, l*64+s]
    trans64<<<BB, 256>>>(scratch, out);
}